// round 6
// baseline (speedup 1.0000x reference)
#include <cuda_runtime.h>
#include <cuda_bf16.h>
#include <cstdint>

#define O_NUM 50000
#define T_NUM 200000
#define N_NUM (O_NUM + T_NUM)
#define D_DIM 128
#define NPART 196           // ceil(O_NUM/256)
#define WBLK  64            // wconv blocks (16384/256)
#define RSQRT2F 0.7071067811865476f

// ---------------- scratch (no allocations allowed) ----------------
__device__ __nv_bfloat16 g_wh[D_DIM * D_DIM];
__device__ __nv_bfloat16 g_wl[D_DIM * D_DIM];
__device__ float     g_dinv[O_NUM];
__device__ int       g_counts[O_NUM];
__device__ int       g_offs[O_NUM + 1];
__device__ int       g_cursor[O_NUM];
__device__ int       g_sorted[T_NUM];
__device__ int       g_part[NPART];
__device__ int       g_stride;
__device__ int       g_doff;

__device__ __forceinline__ int edge_src(const int* e32, int t, int stride) {
    return __ldg(e32 + (size_t)stride * t);
}
__device__ __forceinline__ int edge_dst(const int* e32, int t, int stride, int doff) {
    return __ldg(e32 + (size_t)stride * t + doff);
}
__device__ __forceinline__ const float* row_ptr(int k, const float* obj, const float* pred) {
    return (k < O_NUM) ? (obj + (size_t)k * D_DIM) : (pred + (size_t)(k - O_NUM) * D_DIM);
}

// ---------------- K1: prep = zero counters + W split + edge-dtype detect ----------------
__global__ void prep_kernel(const float* __restrict__ W, const int* __restrict__ e32) {
    int b = blockIdx.x;
    if (b < NPART) {
        int i = b * 256 + threadIdx.x;
        if (i < O_NUM) { g_counts[i] = 0; g_cursor[i] = 0; }
    } else if (b < NPART + WBLK) {
        int i = (b - NPART) * 256 + threadIdx.x;
        float w = W[i];
        __nv_bfloat16 h = __float2bfloat16(w);
        g_wh[i] = h;
        g_wl[i] = __float2bfloat16(w - __bfloat162float(h));
    } else {
        if (threadIdx.x < 32) {
            int acc = 0;
            for (int i = threadIdx.x; i < 4096; i += 32) acc |= e32[2 * i + 1];
            #pragma unroll
            for (int off = 16; off; off >>= 1) acc |= __shfl_xor_sync(0xFFFFFFFFu, acc, off);
            if (threadIdx.x == 0) {
                g_stride = acc ? 2 : 4;
                g_doff   = acc ? 1 : 2;
            }
        }
    }
}

// ---------------- K2: histogram of edges[:,1] ----------------
__global__ void hist_kernel(const int* __restrict__ e32) {
    int t = blockIdx.x * blockDim.x + threadIdx.x;
    if (t < T_NUM) {
        int d = edge_dst(e32, t, g_stride, g_doff);
        atomicAdd(&g_counts[d], 1);
    }
}

// ---------------- K3: per-block exclusive scan ----------------
__global__ __launch_bounds__(256) void scan_block_kernel() {
    int t = threadIdx.x;
    int i = blockIdx.x * 256 + t;
    int lane = t & 31, w = t >> 5;
    int v = (i < O_NUM) ? g_counts[i] : 0;

    int iv = v;
    #pragma unroll
    for (int off = 1; off < 32; off <<= 1) {
        int n = __shfl_up_sync(0xFFFFFFFFu, iv, off);
        if (lane >= off) iv += n;
    }
    __shared__ int ws[8];
    if (lane == 31) ws[w] = iv;
    __syncthreads();
    if (w == 0 && lane < 8) {
        int x = ws[lane];
        #pragma unroll
        for (int off = 1; off < 8; off <<= 1) {
            int n = __shfl_up_sync(0x000000FFu, x, off);
            if (lane >= off) x += n;
        }
        ws[lane] = x;
    }
    __syncthreads();
    int excl = iv - v + (w ? ws[w - 1] : 0);
    if (i < O_NUM) g_offs[i] = excl;
    if (t == 255) g_part[blockIdx.x] = excl + v;
}

// ---------------- K4: fixup (per-block prefix of partials) + dinv ----------------
__global__ __launch_bounds__(256) void scan_fix_kernel() {
    int b = blockIdx.x;
    int t = threadIdx.x;
    int lane = t & 31, w = t >> 5;

    int v = (t < b) ? g_part[t] : 0;
    #pragma unroll
    for (int off = 16; off; off >>= 1) v += __shfl_xor_sync(0xFFFFFFFFu, v, off);
    __shared__ int ws[8];
    if (lane == 0) ws[w] = v;
    __syncthreads();
    __shared__ int base_s;
    if (t == 0) {
        int s = 0;
        #pragma unroll
        for (int q = 0; q < 8; q++) s += ws[q];
        base_s = s;
    }
    __syncthreads();
    int base = base_s;

    int i = b * 256 + t;
    if (i < O_NUM) {
        g_offs[i] += base;
        g_dinv[i] = rsqrtf(2.0f + (float)g_counts[i]);
    }
    if (b == NPART - 1 && t == 0) g_offs[O_NUM] = base + g_part[NPART - 1];
}

// ---------------- K5: counting-sort scatter (build CSR of group-2 sources) ----------------
__global__ void csr_scatter_kernel(const int* __restrict__ e32) {
    int t = blockIdx.x * blockDim.x + threadIdx.x;
    if (t < T_NUM) {
        int d = edge_dst(e32, t, g_stride, g_doff);
        int pos = g_offs[d] + atomicAdd(&g_cursor[d], 1);
        g_sorted[pos] = t;
    }
}

// ---------------- K6: FUSED aggregate + GEMM ----------------
__device__ __forceinline__ void mma16816(float c[4], const uint32_t a[4], const uint32_t b[2]) {
    asm("mma.sync.aligned.m16n8k16.row.col.f32.bf16.bf16.f32 "
        "{%0,%1,%2,%3}, {%4,%5,%6,%7}, {%8,%9}, {%0,%1,%2,%3};"
        : "+f"(c[0]), "+f"(c[1]), "+f"(c[2]), "+f"(c[3])
        : "r"(a[0]), "r"(a[1]), "r"(a[2]), "r"(a[3]), "r"(b[0]), "r"(b[1]));
}

#define LDSY 136   // 128 + 8 bf16 pad -> conflict-free fragment reads
#define SMEM_W_HALF (128 * LDSY)          // elems per W half
#define SMEM_Y_HALF (64 * LDSY)           // elems per Y half
#define FUSED_SMEM_BYTES ((2 * SMEM_W_HALF + 2 * SMEM_Y_HALF) * 2)

__device__ __forceinline__ uint32_t lds32(const __nv_bfloat16* p) {
    return *reinterpret_cast<const uint32_t*>(p);
}

extern __shared__ char sm_raw[];

__global__ __launch_bounds__(256) void fused_kernel(const float* __restrict__ obj,
                                                    const float* __restrict__ pred,
                                                    const int* __restrict__ e32,
                                                    const float* __restrict__ bias,
                                                    float* __restrict__ out) {
    __nv_bfloat16* sWh = reinterpret_cast<__nv_bfloat16*>(sm_raw);
    __nv_bfloat16* sWl = sWh + SMEM_W_HALF;
    __nv_bfloat16* sYh = sWl + SMEM_W_HALF;
    __nv_bfloat16* sYl = sYh + SMEM_Y_HALF;

    int tid  = threadIdx.x;
    int warp = tid >> 5, lane = tid & 31;
    int rowbase = blockIdx.x * 64;
    int stride = g_stride;

    // ---- stage W (both halves), coalesced uint4 ----
    #pragma unroll
    for (int it = 0; it < 8; it++) {
        int r = it * 16 + (tid >> 4);
        int cseg = tid & 15;
        uint4 vh = *reinterpret_cast<const uint4*>(g_wh + r * D_DIM + cseg * 8);
        uint4 vl = *reinterpret_cast<const uint4*>(g_wl + r * D_DIM + cseg * 8);
        *reinterpret_cast<uint4*>(sWh + r * LDSY + cseg * 8) = vh;
        *reinterpret_cast<uint4*>(sWl + r * LDSY + cseg * 8) = vl;
    }

    // ---- gather phase: warp w aggregates local rows [w*8, w*8+8) ----
    int base_n = rowbase + warp * 8;

    // lane-parallel metadata for the 8 rows
    int mrow = base_n + lane;                 // lanes 0..8 used
    int   src8 = 0;
    float ds8  = 0.0f;
    if (lane < 8 && mrow < T_NUM) {
        src8 = edge_src(e32, mrow, stride);
        ds8  = g_dinv[src8];
    }
    int off9 = 0;
    if (lane < 9 && mrow <= O_NUM && base_n < O_NUM) off9 = g_offs[mrow];
    float dn8 = 1.0f;
    if (lane < 8) {
        if (mrow < O_NUM)      dn8 = g_dinv[mrow];
        else if (mrow < T_NUM) dn8 = RSQRT2F;
    }

    // front-batch the 8 self-row loads (independent, fills MLP)
    float4 selfv[8];
    #pragma unroll
    for (int i = 0; i < 8; i++) {
        int n = base_n + i;
        if (n < N_NUM)
            selfv[i] = __ldg(reinterpret_cast<const float4*>(row_ptr(n, obj, pred)) + lane);
        else
            selfv[i] = make_float4(0.f, 0.f, 0.f, 0.f);
    }

    #pragma unroll 1
    for (int i = 0; i < 8; i++) {
        int n = base_n + i;
        int local = warp * 8 + i;
        float4 acc = make_float4(0.f, 0.f, 0.f, 0.f);
        if (n < N_NUM) {
            float dn = __shfl_sync(0xFFFFFFFFu, dn8, i);
            acc.x = selfv[i].x * dn;
            acc.y = selfv[i].y * dn;
            acc.z = selfv[i].z * dn;
            acc.w = selfv[i].w * dn;

            if (n < T_NUM) {
                int   s  = __shfl_sync(0xFFFFFFFFu, src8, i);
                float ds = __shfl_sync(0xFFFFFFFFu, ds8, i);
                const float4* xs = reinterpret_cast<const float4*>(obj + (size_t)s * D_DIM);
                float4 v = __ldg(xs + lane);
                acc.x = fmaf(v.x, ds, acc.x);
                acc.y = fmaf(v.y, ds, acc.y);
                acc.z = fmaf(v.z, ds, acc.z);
                acc.w = fmaf(v.w, ds, acc.w);
            }

            if (n < O_NUM) {
                int beg = __shfl_sync(0xFFFFFFFFu, off9, i);
                int end = __shfl_sync(0xFFFFFFFFu, off9, i + 1);
                int cnt = end - beg;
                for (int bb = 0; bb < cnt; bb += 8) {
                    int m = cnt - bb; if (m > 8) m = 8;
                    int   kid = 0;
                    float dkl = 0.0f;
                    if (lane < m) {
                        kid = g_sorted[beg + bb + lane];
                        dkl = (kid < O_NUM) ? g_dinv[kid] : RSQRT2F;
                    }
                    #pragma unroll
                    for (int q = 0; q < 8; q++) {
                        if (q >= m) break;
                        int   k  = __shfl_sync(0xFFFFFFFFu, kid, q);
                        float dk = __shfl_sync(0xFFFFFFFFu, dkl, q);
                        const float4* xk = reinterpret_cast<const float4*>(row_ptr(k, obj, pred));
                        float4 v = __ldg(xk + lane);
                        acc.x = fmaf(v.x, dk, acc.x);
                        acc.y = fmaf(v.y, dk, acc.y);
                        acc.z = fmaf(v.z, dk, acc.z);
                        acc.w = fmaf(v.w, dk, acc.w);
                    }
                }
            }
            acc.x *= dn; acc.y *= dn; acc.z *= dn; acc.w *= dn;
        }

        // split to bf16 hi/lo into smem
        float v4[4] = {acc.x, acc.y, acc.z, acc.w};
        alignas(8) __nv_bfloat16 h[4];
        alignas(8) __nv_bfloat16 l[4];
        #pragma unroll
        for (int q = 0; q < 4; q++) {
            h[q] = __float2bfloat16(v4[q]);
            l[q] = __float2bfloat16(v4[q] - __bfloat162float(h[q]));
        }
        *reinterpret_cast<uint2*>(sYh + local * LDSY + lane * 4) = *reinterpret_cast<const uint2*>(h);
        *reinterpret_cast<uint2*>(sYl + local * LDSY + lane * 4) = *reinterpret_cast<const uint2*>(l);
    }
    __syncthreads();

    // ---- MMA phase: warp = (band, colhalf); band = warp>>1 (16 rows), colhalf = warp&1 (64 cols)
    int band = warp >> 1;
    int ch   = warp & 1;
    int g  = lane >> 2;
    int tg = lane & 3;

    const __nv_bfloat16* aH0 = sYh + (band * 16 + g) * LDSY;
    const __nv_bfloat16* aL0 = sYl + (band * 16 + g) * LDSY;

    float c[8][4];
    #pragma unroll
    for (int n = 0; n < 8; n++)
        #pragma unroll
        for (int q = 0; q < 4; q++) c[n][q] = 0.0f;

    #pragma unroll
    for (int kt = 0; kt < 8; kt++) {
        int k = kt * 16;
        uint32_t ah[4], al[4];
        ah[0] = lds32(aH0 + k + tg * 2);
        ah[1] = lds32(aH0 + 8 * LDSY + k + tg * 2);
        ah[2] = lds32(aH0 + k + 8 + tg * 2);
        ah[3] = lds32(aH0 + 8 * LDSY + k + 8 + tg * 2);
        al[0] = lds32(aL0 + k + tg * 2);
        al[1] = lds32(aL0 + 8 * LDSY + k + tg * 2);
        al[2] = lds32(aL0 + k + 8 + tg * 2);
        al[3] = lds32(aL0 + 8 * LDSY + k + 8 + tg * 2);

        #pragma unroll
        for (int n = 0; n < 8; n++) {
            int cw = ch * 64 + n * 8 + g;
            const __nv_bfloat16* bH = sWh + cw * LDSY + k + tg * 2;
            const __nv_bfloat16* bL = sWl + cw * LDSY + k + tg * 2;
            uint32_t bh[2] = { lds32(bH), lds32(bH + 8) };
            uint32_t bl[2] = { lds32(bL), lds32(bL + 8) };
            mma16816(c[n], ah, bh);
            mma16816(c[n], al, bh);
            mma16816(c[n], ah, bl);
        }
    }

    int r0 = rowbase + band * 16 + g;
    int r1 = r0 + 8;
    #pragma unroll
    for (int n = 0; n < 8; n++) {
        int col = ch * 64 + n * 8 + tg * 2;
        float2 bb = *reinterpret_cast<const float2*>(bias + col);
        if (r0 < N_NUM) {
            float2 o = make_float2(c[n][0] + bb.x, c[n][1] + bb.y);
            *reinterpret_cast<float2*>(out + (size_t)r0 * D_DIM + col) = o;
        }
        if (r1 < N_NUM) {
            float2 o = make_float2(c[n][2] + bb.x, c[n][3] + bb.y);
            *reinterpret_cast<float2*>(out + (size_t)r1 * D_DIM + col) = o;
        }
    }
}

// ---------------- launch ----------------
extern "C" void kernel_launch(void* const* d_in, const int* in_sizes, int n_in,
                              void* d_out, int out_size) {
    const float* obj   = (const float*)d_in[0];
    const float* pred  = (const float*)d_in[1];
    const int*   e32   = (const int*)d_in[2];
    const float* W     = (const float*)d_in[3];
    const float* bias  = (const float*)d_in[4];
    float*       out   = (float*)d_out;

    cudaFuncSetAttribute(fused_kernel,
                         cudaFuncAttributeMaxDynamicSharedMemorySize, FUSED_SMEM_BYTES);

    prep_kernel<<<NPART + WBLK + 1, 256>>>(W, e32);                 // launch 1
    hist_kernel<<<(T_NUM + 255) / 256, 256>>>(e32);                 // launch 2
    scan_block_kernel<<<NPART, 256>>>();                            // launch 3
    scan_fix_kernel<<<NPART, 256>>>();                              // launch 4
    csr_scatter_kernel<<<(T_NUM + 255) / 256, 256>>>(e32);          // launch 5
    int fused_blocks = (N_NUM + 63) / 64;                           // 3907
    fused_kernel<<<fused_blocks, 256, FUSED_SMEM_BYTES>>>(obj, pred, e32, bias, out);  // launch 6
}

// round 7
// speedup vs baseline: 1.3837x; 1.3837x over previous
#include <cuda_runtime.h>
#include <cuda_bf16.h>
#include <cstdint>

#define O_NUM 50000
#define T_NUM 200000
#define N_NUM (O_NUM + T_NUM)
#define D_DIM 128
#define NPART 196           // ceil(O_NUM/256)
#define WBLK  64            // wconv blocks (16384/256)
#define RSQRT2F 0.7071067811865476f

// ---------------- scratch (no allocations allowed) ----------------
__device__ __nv_bfloat16 g_yh[(size_t)N_NUM * D_DIM];
__device__ __nv_bfloat16 g_yl[(size_t)N_NUM * D_DIM];
__device__ __nv_bfloat16 g_wh[D_DIM * D_DIM];
__device__ __nv_bfloat16 g_wl[D_DIM * D_DIM];
__device__ float     g_dinv[O_NUM];
__device__ int       g_counts[O_NUM];
__device__ int       g_offs[O_NUM + 1];
__device__ int       g_cursor[O_NUM];
__device__ int       g_sorted[T_NUM];
__device__ int       g_part[NPART];
__device__ int       g_stride;
__device__ int       g_doff;

__device__ __forceinline__ int edge_src(const int* e32, int t, int stride) {
    return __ldg(e32 + (size_t)stride * t);
}
__device__ __forceinline__ int edge_dst(const int* e32, int t, int stride, int doff) {
    return __ldg(e32 + (size_t)stride * t + doff);
}
__device__ __forceinline__ const float* row_ptr(int k, const float* obj, const float* pred) {
    return (k < O_NUM) ? (obj + (size_t)k * D_DIM) : (pred + (size_t)(k - O_NUM) * D_DIM);
}

// ---------------- K1: prep = zero counters + W split + edge-dtype detect ----------------
__global__ void prep_kernel(const float* __restrict__ W, const int* __restrict__ e32) {
    int b = blockIdx.x;
    if (b < NPART) {
        int i = b * 256 + threadIdx.x;
        if (i < O_NUM) { g_counts[i] = 0; g_cursor[i] = 0; }
    } else if (b < NPART + WBLK) {
        int i = (b - NPART) * 256 + threadIdx.x;
        float w = W[i];
        __nv_bfloat16 h = __float2bfloat16(w);
        g_wh[i] = h;
        g_wl[i] = __float2bfloat16(w - __bfloat162float(h));
    } else {
        if (threadIdx.x < 32) {
            int acc = 0;
            for (int i = threadIdx.x; i < 4096; i += 32) acc |= e32[2 * i + 1];
            #pragma unroll
            for (int off = 16; off; off >>= 1) acc |= __shfl_xor_sync(0xFFFFFFFFu, acc, off);
            if (threadIdx.x == 0) {
                g_stride = acc ? 2 : 4;
                g_doff   = acc ? 1 : 2;
            }
        }
    }
}

// ---------------- K2: histogram of edges[:,1] ----------------
__global__ void hist_kernel(const int* __restrict__ e32) {
    int t = blockIdx.x * blockDim.x + threadIdx.x;
    if (t < T_NUM) {
        int d = edge_dst(e32, t, g_stride, g_doff);
        atomicAdd(&g_counts[d], 1);
    }
}

// ---------------- K3: per-block exclusive scan ----------------
__global__ __launch_bounds__(256) void scan_block_kernel() {
    int t = threadIdx.x;
    int i = blockIdx.x * 256 + t;
    int lane = t & 31, w = t >> 5;
    int v = (i < O_NUM) ? g_counts[i] : 0;

    int iv = v;
    #pragma unroll
    for (int off = 1; off < 32; off <<= 1) {
        int n = __shfl_up_sync(0xFFFFFFFFu, iv, off);
        if (lane >= off) iv += n;
    }
    __shared__ int ws[8];
    if (lane == 31) ws[w] = iv;
    __syncthreads();
    if (w == 0 && lane < 8) {
        int x = ws[lane];
        #pragma unroll
        for (int off = 1; off < 8; off <<= 1) {
            int n = __shfl_up_sync(0x000000FFu, x, off);
            if (lane >= off) x += n;
        }
        ws[lane] = x;
    }
    __syncthreads();
    int excl = iv - v + (w ? ws[w - 1] : 0);
    if (i < O_NUM) g_offs[i] = excl;
    if (t == 255) g_part[blockIdx.x] = excl + v;
}

// ---------------- K4: fixup (per-block prefix of partials) + dinv ----------------
__global__ __launch_bounds__(256) void scan_fix_kernel() {
    int b = blockIdx.x;
    int t = threadIdx.x;
    int lane = t & 31, w = t >> 5;

    int v = (t < b) ? g_part[t] : 0;
    #pragma unroll
    for (int off = 16; off; off >>= 1) v += __shfl_xor_sync(0xFFFFFFFFu, v, off);
    __shared__ int ws[8];
    if (lane == 0) ws[w] = v;
    __syncthreads();
    __shared__ int base_s;
    if (t == 0) {
        int s = 0;
        #pragma unroll
        for (int q = 0; q < 8; q++) s += ws[q];
        base_s = s;
    }
    __syncthreads();
    int base = base_s;

    int i = b * 256 + t;
    if (i < O_NUM) {
        g_offs[i] += base;
        g_dinv[i] = rsqrtf(2.0f + (float)g_counts[i]);
    }
    if (b == NPART - 1 && t == 0) g_offs[O_NUM] = base + g_part[NPART - 1];
}

// ---------------- K5: counting-sort scatter (build CSR of group-2 sources) ----------------
__global__ void csr_scatter_kernel(const int* __restrict__ e32) {
    int t = blockIdx.x * blockDim.x + threadIdx.x;
    if (t < T_NUM) {
        int d = edge_dst(e32, t, g_stride, g_doff);
        int pos = g_offs[d] + atomicAdd(&g_cursor[d], 1);
        g_sorted[pos] = t;
    }
}

// ---------------- K6: aggregation, warp per row, batched MLP gathers ----------------
__global__ __launch_bounds__(256) void aggregate_kernel(const float* __restrict__ obj,
                                                        const float* __restrict__ pred,
                                                        const int* __restrict__ e32) {
    int gwarp = (blockIdx.x * blockDim.x + threadIdx.x) >> 5;
    int lane  = threadIdx.x & 31;
    if (gwarp >= N_NUM) return;
    int n = gwarp;
    float dn = (n < O_NUM) ? g_dinv[n] : ((n < T_NUM) ? RSQRT2F : 1.0f);

    const float4* xn = reinterpret_cast<const float4*>(row_ptr(n, obj, pred));
    float4 a = __ldg(xn + lane);

    float4 v1 = make_float4(0.f, 0.f, 0.f, 0.f);
    float  ds = 0.0f;
    if (n < T_NUM) {
        int s = edge_src(e32, n, g_stride);
        ds = g_dinv[s];
        const float4* xs = reinterpret_cast<const float4*>(obj + (size_t)s * D_DIM);
        v1 = __ldg(xs + lane);
    }

    float4 acc;
    acc.x = fmaf(v1.x, ds, a.x * dn);
    acc.y = fmaf(v1.y, ds, a.y * dn);
    acc.z = fmaf(v1.z, ds, a.z * dn);
    acc.w = fmaf(v1.w, ds, a.w * dn);

    if (n < O_NUM) {
        int beg = g_offs[n];
        int cnt = g_offs[n + 1] - beg;
        for (int bb = 0; bb < cnt; bb += 8) {
            int m = cnt - bb; if (m > 8) m = 8;
            int   kid = 0;
            float dkl = 0.0f;
            if (lane < m) {
                kid = g_sorted[beg + bb + lane];
                dkl = (kid < O_NUM) ? g_dinv[kid] : RSQRT2F;
            }
            #pragma unroll
            for (int i = 0; i < 8; i++) {
                if (i >= m) break;
                int   k  = __shfl_sync(0xFFFFFFFFu, kid, i);
                float dk = __shfl_sync(0xFFFFFFFFu, dkl, i);
                const float4* xk = reinterpret_cast<const float4*>(row_ptr(k, obj, pred));
                float4 v = __ldg(xk + lane);
                acc.x = fmaf(v.x, dk, acc.x);
                acc.y = fmaf(v.y, dk, acc.y);
                acc.z = fmaf(v.z, dk, acc.z);
                acc.w = fmaf(v.w, dk, acc.w);
            }
        }
    }

    acc.x *= dn; acc.y *= dn; acc.z *= dn; acc.w *= dn;

    float v4[4] = {acc.x, acc.y, acc.z, acc.w};
    alignas(8) __nv_bfloat16 h[4];
    alignas(8) __nv_bfloat16 l[4];
    #pragma unroll
    for (int i = 0; i < 4; i++) {
        h[i] = __float2bfloat16(v4[i]);
        l[i] = __float2bfloat16(v4[i] - __bfloat162float(h[i]));
    }
    size_t base = (size_t)n * D_DIM + lane * 4;
    *reinterpret_cast<uint2*>(g_yh + base) = *reinterpret_cast<const uint2*>(h);
    *reinterpret_cast<uint2*>(g_yl + base) = *reinterpret_cast<const uint2*>(l);
}

// ---------------- K7: out = Y @ W^T + b, 64-row tiles, 2 CTAs/SM ----------------
__device__ __forceinline__ void mma16816(float c[4], const uint32_t a[4], const uint32_t b[2]) {
    asm("mma.sync.aligned.m16n8k16.row.col.f32.bf16.bf16.f32 "
        "{%0,%1,%2,%3}, {%4,%5,%6,%7}, {%8,%9}, {%0,%1,%2,%3};"
        : "+f"(c[0]), "+f"(c[1]), "+f"(c[2]), "+f"(c[3])
        : "r"(a[0]), "r"(a[1]), "r"(a[2]), "r"(a[3]), "r"(b[0]), "r"(b[1]));
}

#define LDSY 136   // 128 + 8 bf16 pad -> conflict-free fragment reads
#define SMEM_W_HALF (128 * LDSY)          // elems per W half
#define SMEM_Y_HALF (64 * LDSY)           // elems per Y half (64 rows)
#define GEMM_SMEM_BYTES ((2 * SMEM_W_HALF + 2 * SMEM_Y_HALF) * 2)   // ~104.4 KB

__device__ __forceinline__ uint32_t lds32(const __nv_bfloat16* p) {
    return *reinterpret_cast<const uint32_t*>(p);
}

extern __shared__ char sm_raw[];

__global__ __launch_bounds__(256) void gemm_mma_kernel(const float* __restrict__ bias,
                                                       float* __restrict__ out) {
    __nv_bfloat16* sWh = reinterpret_cast<__nv_bfloat16*>(sm_raw);
    __nv_bfloat16* sWl = sWh + SMEM_W_HALF;
    __nv_bfloat16* sYh = sWl + SMEM_W_HALF;
    __nv_bfloat16* sYl = sYh + SMEM_Y_HALF;

    int tid  = threadIdx.x;
    int warp = tid >> 5, lane = tid & 31;
    int g  = lane >> 2;
    int tg = lane & 3;
    int rowbase = blockIdx.x * 64;

    // stage W (both halves), coalesced uint4
    #pragma unroll
    for (int it = 0; it < 8; it++) {
        int r = it * 16 + (tid >> 4);
        int cseg = tid & 15;
        uint4 vh = *reinterpret_cast<const uint4*>(g_wh + r * D_DIM + cseg * 8);
        uint4 vl = *reinterpret_cast<const uint4*>(g_wl + r * D_DIM + cseg * 8);
        *reinterpret_cast<uint4*>(sWh + r * LDSY + cseg * 8) = vh;
        *reinterpret_cast<uint4*>(sWl + r * LDSY + cseg * 8) = vl;
    }
    // stage Y tile (64 rows), zero-fill OOB rows
    #pragma unroll
    for (int it = 0; it < 4; it++) {
        int r = it * 16 + (tid >> 4);
        int cseg = tid & 15;
        int grow = rowbase + r;
        uint4 vh = make_uint4(0u, 0u, 0u, 0u), vl = vh;
        if (grow < N_NUM) {
            vh = *reinterpret_cast<const uint4*>(g_yh + (size_t)grow * D_DIM + cseg * 8);
            vl = *reinterpret_cast<const uint4*>(g_yl + (size_t)grow * D_DIM + cseg * 8);
        }
        *reinterpret_cast<uint4*>(sYh + r * LDSY + cseg * 8) = vh;
        *reinterpret_cast<uint4*>(sYl + r * LDSY + cseg * 8) = vl;
    }
    __syncthreads();

    // warp = (band, colhalf): band = warp>>1 (16 rows), colhalf = warp&1 (64 cols)
    int band = warp >> 1;
    int ch   = warp & 1;

    const __nv_bfloat16* aH0 = sYh + (band * 16 + g) * LDSY;
    const __nv_bfloat16* aL0 = sYl + (band * 16 + g) * LDSY;

    float c[8][4];
    #pragma unroll
    for (int n = 0; n < 8; n++)
        #pragma unroll
        for (int q = 0; q < 4; q++) c[n][q] = 0.0f;

    #pragma unroll
    for (int kt = 0; kt < 8; kt++) {
        int k = kt * 16;
        uint32_t ah[4], al[4];
        ah[0] = lds32(aH0 + k + tg * 2);
        ah[1] = lds32(aH0 + 8 * LDSY + k + tg * 2);
        ah[2] = lds32(aH0 + k + 8 + tg * 2);
        ah[3] = lds32(aH0 + 8 * LDSY + k + 8 + tg * 2);
        al[0] = lds32(aL0 + k + tg * 2);
        al[1] = lds32(aL0 + 8 * LDSY + k + tg * 2);
        al[2] = lds32(aL0 + k + 8 + tg * 2);
        al[3] = lds32(aL0 + 8 * LDSY + k + 8 + tg * 2);

        #pragma unroll
        for (int n = 0; n < 8; n++) {
            int cw = ch * 64 + n * 8 + g;
            const __nv_bfloat16* bH = sWh + cw * LDSY + k + tg * 2;
            const __nv_bfloat16* bL = sWl + cw * LDSY + k + tg * 2;
            uint32_t bh[2] = { lds32(bH), lds32(bH + 8) };
            uint32_t bl[2] = { lds32(bL), lds32(bL + 8) };
            mma16816(c[n], ah, bh);
            mma16816(c[n], al, bh);
            mma16816(c[n], ah, bl);
        }
    }

    int r0 = rowbase + band * 16 + g;
    int r1 = r0 + 8;
    #pragma unroll
    for (int n = 0; n < 8; n++) {
        int col = ch * 64 + n * 8 + tg * 2;
        float2 bb = *reinterpret_cast<const float2*>(bias + col);
        if (r0 < N_NUM) {
            float2 o = make_float2(c[n][0] + bb.x, c[n][1] + bb.y);
            *reinterpret_cast<float2*>(out + (size_t)r0 * D_DIM + col) = o;
        }
        if (r1 < N_NUM) {
            float2 o = make_float2(c[n][2] + bb.x, c[n][3] + bb.y);
            *reinterpret_cast<float2*>(out + (size_t)r1 * D_DIM + col) = o;
        }
    }
}

// ---------------- launch ----------------
extern "C" void kernel_launch(void* const* d_in, const int* in_sizes, int n_in,
                              void* d_out, int out_size) {
    const float* obj   = (const float*)d_in[0];
    const float* pred  = (const float*)d_in[1];
    const int*   e32   = (const int*)d_in[2];
    const float* W     = (const float*)d_in[3];
    const float* bias  = (const float*)d_in[4];
    float*       out   = (float*)d_out;

    cudaFuncSetAttribute(gemm_mma_kernel,
                         cudaFuncAttributeMaxDynamicSharedMemorySize, GEMM_SMEM_BYTES);

    prep_kernel<<<NPART + WBLK + 1, 256>>>(W, e32);                 // launch 1
    hist_kernel<<<(T_NUM + 255) / 256, 256>>>(e32);                 // launch 2
    scan_block_kernel<<<NPART, 256>>>();                            // launch 3
    scan_fix_kernel<<<NPART, 256>>>();                              // launch 4
    csr_scatter_kernel<<<(T_NUM + 255) / 256, 256>>>(e32);          // launch 5
    aggregate_kernel<<<(N_NUM + 7) / 8, 256>>>(obj, pred, e32);     // launch 6
    gemm_mma_kernel<<<(N_NUM + 63) / 64, 256, GEMM_SMEM_BYTES>>>(bias, out);  // launch 7
}